// round 1
// baseline (speedup 1.0000x reference)
#include <cuda_runtime.h>

// Problem constants
#define N_T 32          // tube length
#define NF  17          // rfft bins: N_T/2 + 1
#define SIZE 1024       // P = Q = M = 1024
#define PQ  1048576     // 1024*1024 elements per slice

// Scratch in device globals (allocation-free rule)
__device__ float2 g_Wf[NF * PQ];   // rfft(weights) per freq: [k][p][q]
__device__ float2 g_Xf[NF * PQ];   // rfft(x) per freq:       [k][q][m]
__device__ float2 g_Cf[NF * PQ];   // Wf @ Xf per freq:       [k][p][m]

// ---------------------------------------------------------------------------
// Forward DFT-32 (rfft) along the tube dim. One thread per (row,col) column.
// in:  real [32][1024][1024]   out: complex [17][1024][1024]
// ---------------------------------------------------------------------------
__global__ __launch_bounds__(256) void fft32_kernel(const float* __restrict__ in,
                                                    float2* __restrict__ out) {
    __shared__ float2 tw[32];   // tw[j] = (cos(2*pi*j/32), sin(2*pi*j/32))
    int t = threadIdx.x;
    if (t < 32) {
        float s, c;
        sincospif(t * (1.0f / 16.0f), &s, &c);
        tw[t] = make_float2(c, s);
    }
    __syncthreads();

    int idx = blockIdx.x * blockDim.x + t;   // 0 .. PQ-1

    float v[N_T];
    #pragma unroll
    for (int n = 0; n < N_T; n++) v[n] = in[n * PQ + idx];

    #pragma unroll 1
    for (int k = 0; k < NF; k++) {
        float re = 0.0f, im = 0.0f;
        int j = 0;
        #pragma unroll
        for (int n = 0; n < N_T; n++) {
            float2 w = tw[j];
            re += v[n] * w.x;     // e^{-i theta}: cos
            im -= v[n] * w.y;     //              -sin
            j = (j + k) & 31;
        }
        out[k * PQ + idx] = make_float2(re, im);
    }
}

// ---------------------------------------------------------------------------
// Complex GEMM per frequency: Cf[k] = Wf[k](PxQ) @ Xf[k](QxM)
// 64x64 tile, BK=16, 256 threads, 4x4 complex outputs per thread.
// ---------------------------------------------------------------------------
#define BM 64
#define BN 64
#define BK 16

__global__ __launch_bounds__(256) void cgemm_kernel(const float2* __restrict__ Aall,
                                                    const float2* __restrict__ Ball,
                                                    float2* __restrict__ Call) {
    const float2* A = Aall + (size_t)blockIdx.z * PQ;
    const float2* B = Ball + (size_t)blockIdx.z * PQ;
    float2*       C = Call + (size_t)blockIdx.z * PQ;

    __shared__ float2 As[BK][BM + 1];  // transposed A tile, padded vs conflicts
    __shared__ float2 Bs[BK][BN];

    int t  = threadIdx.x;
    int tx = t & 15;        // output col group
    int ty = t >> 4;        // output row group
    int row0 = blockIdx.y * BM;
    int col0 = blockIdx.x * BN;

    float accx[4][4] = {};
    float accy[4][4] = {};

    for (int k0 = 0; k0 < SIZE; k0 += BK) {
        // Load A tile (64 rows x 16 k), store transposed As[k][row]
        #pragma unroll
        for (int i = 0; i < 4; i++) {
            int idx = t + i * 256;
            int r  = idx >> 4;
            int cc = idx & 15;
            As[cc][r] = A[(row0 + r) * SIZE + (k0 + cc)];
        }
        // Load B tile (16 k x 64 cols)
        #pragma unroll
        for (int i = 0; i < 4; i++) {
            int idx = t + i * 256;
            int r  = idx >> 6;
            int cc = idx & 63;
            Bs[r][cc] = B[(k0 + r) * SIZE + (col0 + cc)];
        }
        __syncthreads();

        #pragma unroll
        for (int kk = 0; kk < BK; kk++) {
            float2 a[4], b[4];
            #pragma unroll
            for (int i = 0; i < 4; i++) a[i] = As[kk][ty * 4 + i];
            #pragma unroll
            for (int j = 0; j < 4; j++) b[j] = Bs[kk][tx * 4 + j];
            #pragma unroll
            for (int i = 0; i < 4; i++) {
                #pragma unroll
                for (int j = 0; j < 4; j++) {
                    accx[i][j] += a[i].x * b[j].x;
                    accx[i][j] -= a[i].y * b[j].y;
                    accy[i][j] += a[i].x * b[j].y;
                    accy[i][j] += a[i].y * b[j].x;
                }
            }
        }
        __syncthreads();
    }

    #pragma unroll
    for (int i = 0; i < 4; i++) {
        #pragma unroll
        for (int j = 0; j < 4; j++) {
            C[(row0 + ty * 4 + i) * SIZE + (col0 + tx * 4 + j)] =
                make_float2(accx[i][j], accy[i][j]);
        }
    }
}

// ---------------------------------------------------------------------------
// Inverse DFT-32 (hermitian) + bias. One thread per (p,m).
// out[n] = (1/32) * [ C0 + (-1)^n C16 + 2*sum_{k=1..15} Re(Ck e^{+i 2pi k n/32}) ] + bias
// ---------------------------------------------------------------------------
__global__ __launch_bounds__(256) void ifft32_bias_kernel(const float2* __restrict__ Cf,
                                                          const float* __restrict__ bias,
                                                          float* __restrict__ out) {
    __shared__ float2 tw[32];
    int t = threadIdx.x;
    if (t < 32) {
        float s, c;
        sincospif(t * (1.0f / 16.0f), &s, &c);
        tw[t] = make_float2(c, s);
    }
    __syncthreads();

    int idx = blockIdx.x * blockDim.x + t;   // 0 .. PQ-1

    float2 cv[NF];
    #pragma unroll
    for (int k = 0; k < NF; k++) cv[k] = Cf[k * PQ + idx];
    // pre-scale middle bins by 2 (hermitian doubling)
    #pragma unroll
    for (int k = 1; k < 16; k++) { cv[k].x *= 2.0f; cv[k].y *= 2.0f; }

    float b = bias[idx];

    #pragma unroll 1
    for (int n = 0; n < N_T; n++) {
        float s = cv[0].x + ((n & 1) ? -cv[16].x : cv[16].x);
        int j = n & 31;
        #pragma unroll
        for (int k = 1; k < 16; k++) {
            int jj = (k * n) & 31;
            float2 w = tw[jj];
            // Re(Ck * e^{+i theta}) = Ck.x*cos - Ck.y*sin
            s += cv[k].x * w.x;
            s -= cv[k].y * w.y;
        }
        (void)j;
        out[n * PQ + idx] = s * (1.0f / 32.0f) + b;
    }
}

// ---------------------------------------------------------------------------
// Launch
// ---------------------------------------------------------------------------
extern "C" void kernel_launch(void* const* d_in, const int* in_sizes, int n_in,
                              void* d_out, int out_size) {
    const float* x    = (const float*)d_in[0];   // (32, 1024, 1024)
    const float* w    = (const float*)d_in[1];   // (32, 1024, 1024)
    const float* bias = (const float*)d_in[2];   // (1, 1024, 1024)
    float*       out  = (float*)d_out;           // (32, 1024, 1024)

    float2 *Wf, *Xf, *Cfp;
    cudaGetSymbolAddress((void**)&Wf,  g_Wf);
    cudaGetSymbolAddress((void**)&Xf,  g_Xf);
    cudaGetSymbolAddress((void**)&Cfp, g_Cf);

    const int threads = 256;
    const int blocks  = PQ / threads;   // 4096

    fft32_kernel<<<blocks, threads>>>(w, Wf);
    fft32_kernel<<<blocks, threads>>>(x, Xf);

    dim3 gemm_grid(SIZE / BN, SIZE / BM, NF);   // (16, 16, 17)
    cgemm_kernel<<<gemm_grid, 256>>>(Wf, Xf, Cfp);

    ifft32_bias_kernel<<<blocks, threads>>>(Cfp, bias, out);
}

// round 4
// speedup vs baseline: 2.4404x; 2.4404x over previous
#include <cuda_runtime.h>
#include <cuda_bf16.h>
#include <cstdint>

#define N_T 32
#define NF  17
#define SIZE 1024
#define PQ  1048576
#define KE  2048            // embedded A rows/cols and GEMM K

// GEMM tiling
#define BM 128
#define BN 128
#define KC 64               // bf16 K per chunk (128 bytes per row)
#define NC (KE / KC)        // 32 chunks
#define STAGE_BYTES 65536   // Ah(16K)+Al(16K)+Bh(16K)+Bl(16K)
#define OFF_AH 0
#define OFF_AL 16384
#define OFF_BH 32768
#define OFF_BL 49152

// ---------------------------------------------------------------------------
// Device scratch (allocation-free rule)
// ---------------------------------------------------------------------------
__device__ __nv_bfloat16 g_Ah[(size_t)NF * KE * KE];
__device__ __nv_bfloat16 g_Al[(size_t)NF * KE * KE];
__device__ __nv_bfloat16 g_Bh[(size_t)NF * SIZE * KE];
__device__ __nv_bfloat16 g_Bl[(size_t)NF * SIZE * KE];
__device__ float         g_Cre[(size_t)NF * PQ];
__device__ float         g_Cim[(size_t)NF * PQ];

// ---------------------------------------------------------------------------
// PTX helpers (baseline PTX only — no 'a'-suffix features)
// ---------------------------------------------------------------------------
__device__ __forceinline__ uint32_t smem_u32(const void* p) {
    uint32_t a;
    asm("{ .reg .u64 t; cvta.to.shared.u64 t, %1; cvt.u32.u64 %0, t; }"
        : "=r"(a) : "l"(p));
    return a;
}

__device__ __forceinline__ void cpa16(uint32_t dst, const void* src) {
    asm volatile("cp.async.cg.shared.global [%0], [%1], 16;" :: "r"(dst), "l"(src) : "memory");
}
#define CP_COMMIT() asm volatile("cp.async.commit_group;" ::: "memory")
#define CP_WAIT1()  asm volatile("cp.async.wait_group 1;"  ::: "memory")

__device__ __forceinline__ void ldsm4(uint32_t* r, uint32_t addr) {
    asm volatile("ldmatrix.sync.aligned.m8n8.x4.shared.b16 {%0,%1,%2,%3}, [%4];"
                 : "=r"(r[0]), "=r"(r[1]), "=r"(r[2]), "=r"(r[3]) : "r"(addr));
}

__device__ __forceinline__ void mma16816(float* d, const uint32_t* a, const uint32_t* b) {
    asm volatile("mma.sync.aligned.m16n8k16.row.col.f32.bf16.bf16.f32 "
                 "{%0,%1,%2,%3}, {%4,%5,%6,%7}, {%8,%9}, {%0,%1,%2,%3};"
                 : "+f"(d[0]), "+f"(d[1]), "+f"(d[2]), "+f"(d[3])
                 : "r"(a[0]), "r"(a[1]), "r"(a[2]), "r"(a[3]), "r"(b[0]), "r"(b[1]));
}

// ---------------------------------------------------------------------------
// Prep A: DFT-32 of weights -> embedded split-bf16 A matrices
// Ae = [[Re, -Im],[Im, Re]]  per freq, rows/cols in [0,2048)
// ---------------------------------------------------------------------------
__global__ __launch_bounds__(256) void prepA(const float* __restrict__ w) {
    __shared__ float2 tw[32];
    int t = threadIdx.x;
    if (t < 32) { float s, c; sincospif(t * (1.0f / 16.0f), &s, &c); tw[t] = make_float2(c, s); }
    __syncthreads();

    int idx = blockIdx.x * 256 + t;            // p*1024 + q
    int p = idx >> 10, q = idx & 1023;

    float v[N_T];
    #pragma unroll
    for (int n = 0; n < N_T; n++) v[n] = w[n * PQ + idx];

    #pragma unroll 1
    for (int k = 0; k < NF; k++) {
        float re = 0.0f, im = 0.0f;
        int j = 0;
        #pragma unroll
        for (int n = 0; n < N_T; n++) {
            float2 wv = tw[j];
            re += v[n] * wv.x;
            im -= v[n] * wv.y;
            j = (j + k) & 31;
        }
        __nv_bfloat16 reh = __float2bfloat16(re);
        __nv_bfloat16 rel = __float2bfloat16(re - __bfloat162float(reh));
        __nv_bfloat16 imh = __float2bfloat16(im);
        __nv_bfloat16 iml = __float2bfloat16(im - __bfloat162float(imh));

        size_t base = (size_t)k * KE * KE;
        size_t r0 = base + (size_t)p * KE;
        size_t r1 = base + (size_t)(1024 + p) * KE;
        g_Ah[r0 + q]        = reh;
        g_Ah[r0 + 1024 + q] = __hneg(imh);
        g_Ah[r1 + q]        = imh;
        g_Ah[r1 + 1024 + q] = reh;
        g_Al[r0 + q]        = rel;
        g_Al[r0 + 1024 + q] = __hneg(iml);
        g_Al[r1 + q]        = iml;
        g_Al[r1 + 1024 + q] = rel;
    }
}

// ---------------------------------------------------------------------------
// Prep B: DFT-32 of x -> split-bf16 B^T matrices, K-major [m][kappa]
// kappa in [0,1024) = Re rows, [1024,2048) = Im rows. SMEM 32x32 transpose.
// ---------------------------------------------------------------------------
__global__ __launch_bounds__(1024) void prepB(const float* __restrict__ x) {
    __shared__ float2 tw[32];
    __shared__ __nv_bfloat16 sreh[32][33], srel[32][33], simh[32][33], siml[32][33];
    int t = threadIdx.x;
    if (t < 32) { float s, c; sincospif(t * (1.0f / 16.0f), &s, &c); tw[t] = make_float2(c, s); }
    __syncthreads();

    int bm = blockIdx.x & 31, bq = blockIdx.x >> 5;
    int lm = t & 31, lq = t >> 5;
    int q = bq * 32 + lq, m = bm * 32 + lm;

    float v[N_T];
    #pragma unroll
    for (int n = 0; n < N_T; n++) v[n] = x[(size_t)n * PQ + q * 1024 + m];

    #pragma unroll 1
    for (int k = 0; k < NF; k++) {
        float re = 0.0f, im = 0.0f;
        int j = 0;
        #pragma unroll
        for (int n = 0; n < N_T; n++) {
            float2 wv = tw[j];
            re += v[n] * wv.x;
            im -= v[n] * wv.y;
            j = (j + k) & 31;
        }
        __nv_bfloat16 reh = __float2bfloat16(re);
        __nv_bfloat16 rel = __float2bfloat16(re - __bfloat162float(reh));
        __nv_bfloat16 imh = __float2bfloat16(im);
        __nv_bfloat16 iml = __float2bfloat16(im - __bfloat162float(imh));

        __syncthreads();               // protect planes from previous k
        sreh[lq][lm] = reh;  srel[lq][lm] = rel;
        simh[lq][lm] = imh;  siml[lq][lm] = iml;
        __syncthreads();

        // write transposed: row m' = bm*32+lq, col q' = bq*32+lm (coalesced over lm)
        size_t rowbase = (size_t)k * SIZE * KE + (size_t)(bm * 32 + lq) * KE + bq * 32;
        g_Bh[rowbase + lm]        = sreh[lm][lq];
        g_Bh[rowbase + 1024 + lm] = simh[lm][lq];
        g_Bl[rowbase + lm]        = srel[lm][lq];
        g_Bl[rowbase + 1024 + lm] = siml[lm][lq];
    }
}

// ---------------------------------------------------------------------------
// mma.sync bf16 GEMM: D[2048x1024] = Ah*Bh + Al*Bh + Ah*Bl per freq (fp32 acc)
// 128x128 CTA tile, 8 warps (4m x 2n), warp tile 32x64, 3-stage cp.async.
// ---------------------------------------------------------------------------
__global__ __launch_bounds__(256, 1) void tgemm() {
    extern __shared__ char dynsmem[];
    uint32_t sbase = (smem_u32(dynsmem) + 1023u) & ~1023u;

    const int t = threadIdx.x;
    const int lane = t & 31;
    const int wid = t >> 5;
    const int wm = wid >> 1, wn = wid & 1;
    const int m_warp = wm * 32, n_warp = wn * 64;

    const int kf = blockIdx.z;
    const size_t aoff = (size_t)kf * KE * KE + (size_t)blockIdx.y * BM * KE;
    const size_t boff = (size_t)kf * SIZE * KE + (size_t)blockIdx.x * BN * KE;

    // ldmatrix lane mappings
    const int rowA_off = (lane & 7) + ((lane >> 3) & 1) * 8;  // matrices 0/1 = m halves
    const int kselA    = lane >> 4;                            // matrices 2/3 = k halves
    const int rowB_off = (lane & 7) + ((lane >> 4) & 1) * 8;  // matrices 2/3 = n halves
    const int kselB    = (lane >> 3) & 1;                      // matrices 1/3 = k halves

    // per-chunk cooperative copy: 1024 units = 128 rows x 8 16B-chunks, 256 thr
    auto copy_chunk = [&](int c) {
        uint32_t sb = sbase + (uint32_t)(c % 3) * STAGE_BYTES;
        size_t kcol = (size_t)c * KC;
        #pragma unroll
        for (int i = 0; i < 4; i++) {
            int u = t + i * 256;
            int r = u >> 3, c16 = u & 7;
            uint32_t sw = (uint32_t)(r * 128 + ((c16 ^ (r & 7)) << 4));
            size_t ga = aoff + (size_t)r * KE + kcol + c16 * 8;
            size_t gb = boff + (size_t)r * KE + kcol + c16 * 8;
            cpa16(sb + OFF_AH + sw, g_Ah + ga);
            cpa16(sb + OFF_AL + sw, g_Al + ga);
            cpa16(sb + OFF_BH + sw, g_Bh + gb);
            cpa16(sb + OFF_BL + sw, g_Bl + gb);
        }
    };

    float acc[2][8][4];
    #pragma unroll
    for (int i = 0; i < 2; i++)
        #pragma unroll
        for (int j = 0; j < 8; j++)
            #pragma unroll
            for (int r = 0; r < 4; r++) acc[i][j][r] = 0.0f;

    copy_chunk(0); CP_COMMIT();
    copy_chunk(1); CP_COMMIT();

    for (int c = 0; c < NC; c++) {
        CP_WAIT1();
        __syncthreads();
        uint32_t sb = sbase + (uint32_t)(c % 3) * STAGE_BYTES;

        #pragma unroll
        for (int ks = 0; ks < 4; ks++) {
            uint32_t ah[2][4], al[2][4], bh[4][4], bl[4][4];
            #pragma unroll
            for (int mt = 0; mt < 2; mt++) {
                int row = m_warp + mt * 16 + rowA_off;
                int kch = ks * 2 + kselA;
                uint32_t off = (uint32_t)(row * 128 + (((kch) ^ (row & 7)) << 4));
                ldsm4(ah[mt], sb + OFF_AH + off);
                ldsm4(al[mt], sb + OFF_AL + off);
            }
            #pragma unroll
            for (int nt2 = 0; nt2 < 4; nt2++) {
                int row = n_warp + nt2 * 16 + rowB_off;
                int kch = ks * 2 + kselB;
                uint32_t off = (uint32_t)(row * 128 + (((kch) ^ (row & 7)) << 4));
                ldsm4(bh[nt2], sb + OFF_BH + off);
                ldsm4(bl[nt2], sb + OFF_BL + off);
            }
            #pragma unroll
            for (int mt = 0; mt < 2; mt++) {
                #pragma unroll
                for (int nt = 0; nt < 8; nt++) {
                    const uint32_t* Bh = &bh[nt >> 1][(nt & 1) * 2];
                    const uint32_t* Bl = &bl[nt >> 1][(nt & 1) * 2];
                    mma16816(acc[mt][nt], ah[mt], Bh);
                    mma16816(acc[mt][nt], al[mt], Bh);
                    mma16816(acc[mt][nt], ah[mt], Bl);
                }
            }
        }
        if (c + 2 < NC) copy_chunk(c + 2);
        CP_COMMIT();
    }

    // epilogue: planar C write (rows 0-1023 -> Cre, 1024-2047 -> Cim)
    const int qd = lane >> 2, rr = lane & 3;
    const int rowblk = blockIdx.y * BM;          // entire CTA tile is one plane
    float* plane = (rowblk < 1024) ? g_Cre : g_Cim;
    const size_t pbase = (size_t)kf * PQ + (size_t)((rowblk < 1024) ? rowblk : rowblk - 1024) * 1024
                         + blockIdx.x * BN;

    #pragma unroll
    for (int mt = 0; mt < 2; mt++) {
        #pragma unroll
        for (int half = 0; half < 2; half++) {
            int row = m_warp + mt * 16 + qd + half * 8;
            float* dst = plane + pbase + (size_t)row * 1024;
            #pragma unroll
            for (int nt = 0; nt < 8; nt++) {
                int n = n_warp + nt * 8 + rr * 2;
                *reinterpret_cast<float2*>(dst + n) =
                    make_float2(acc[mt][nt][half * 2], acc[mt][nt][half * 2 + 1]);
            }
        }
    }
}

// ---------------------------------------------------------------------------
// Inverse DFT-32 (hermitian) + bias
// ---------------------------------------------------------------------------
__global__ __launch_bounds__(256) void ifft32_bias_kernel(const float* __restrict__ bias,
                                                          float* __restrict__ out) {
    __shared__ float2 tw[32];
    int t = threadIdx.x;
    if (t < 32) { float s, c; sincospif(t * (1.0f / 16.0f), &s, &c); tw[t] = make_float2(c, s); }
    __syncthreads();

    int idx = blockIdx.x * 256 + t;

    float2 cv[NF];
    #pragma unroll
    for (int k = 0; k < NF; k++) {
        cv[k].x = g_Cre[(size_t)k * PQ + idx];
        cv[k].y = g_Cim[(size_t)k * PQ + idx];
    }
    #pragma unroll
    for (int k = 1; k < 16; k++) { cv[k].x *= 2.0f; cv[k].y *= 2.0f; }

    float b = bias[idx];

    #pragma unroll 1
    for (int n = 0; n < N_T; n++) {
        float s = cv[0].x + ((n & 1) ? -cv[16].x : cv[16].x);
        #pragma unroll
        for (int k = 1; k < 16; k++) {
            int jj = (k * n) & 31;
            float2 wv = tw[jj];
            s += cv[k].x * wv.x;
            s -= cv[k].y * wv.y;
        }
        out[n * PQ + idx] = s * (1.0f / 32.0f) + b;
    }
}

// ---------------------------------------------------------------------------
// Launch
// ---------------------------------------------------------------------------
extern "C" void kernel_launch(void* const* d_in, const int* in_sizes, int n_in,
                              void* d_out, int out_size) {
    const float* x    = (const float*)d_in[0];
    const float* w    = (const float*)d_in[1];
    const float* bias = (const float*)d_in[2];
    float*       out  = (float*)d_out;

    cudaFuncSetAttribute(tgemm, cudaFuncAttributeMaxDynamicSharedMemorySize, 197632);

    prepA<<<4096, 256>>>(w);
    prepB<<<1024, 1024>>>(x);

    dim3 gg(SIZE / BN, KE / BM, NF);   // (8, 16, 17)
    tgemm<<<gg, 256, 197632>>>();

    ifft32_bias_kernel<<<4096, 256>>>(bias, out);
}

// round 5
// speedup vs baseline: 4.1591x; 1.7043x over previous
#include <cuda_runtime.h>
#include <cuda_fp16.h>
#include <cstdint>

#define N_T 32
#define NF  17
#define SIZE 1024
#define PQ  1048576
#define KE  2048            // embedded A rows/cols and GEMM K

// GEMM tiling
#define BM 128
#define BN 128
#define KC 64               // fp16 K per chunk (128 bytes per row)
#define NC (KE / KC)        // 32 chunks
#define NSTAGE 4
#define STAGE_BYTES 32768   // A(16K)+B(16K)
#define OFF_A 0
#define OFF_B 16384

// ---------------------------------------------------------------------------
// Device scratch (allocation-free rule)
// ---------------------------------------------------------------------------
__device__ __half g_A[(size_t)NF * KE * KE];     // embedded [[Re,-Im],[Im,Re]]
__device__ __half g_B[(size_t)NF * SIZE * KE];   // B^T K-major [m][kappa]
__device__ float  g_Cre[(size_t)NF * PQ];
__device__ float  g_Cim[(size_t)NF * PQ];

// ---------------------------------------------------------------------------
// PTX helpers (baseline PTX only — no 'a'-suffix features)
// ---------------------------------------------------------------------------
__device__ __forceinline__ uint32_t smem_u32(const void* p) {
    uint32_t a;
    asm("{ .reg .u64 t; cvta.to.shared.u64 t, %1; cvt.u32.u64 %0, t; }"
        : "=r"(a) : "l"(p));
    return a;
}

__device__ __forceinline__ void cpa16(uint32_t dst, const void* src) {
    asm volatile("cp.async.cg.shared.global [%0], [%1], 16;" :: "r"(dst), "l"(src) : "memory");
}
#define CP_COMMIT() asm volatile("cp.async.commit_group;" ::: "memory")
#define CP_WAIT2()  asm volatile("cp.async.wait_group 2;"  ::: "memory")

__device__ __forceinline__ void ldsm4(uint32_t* r, uint32_t addr) {
    asm volatile("ldmatrix.sync.aligned.m8n8.x4.shared.b16 {%0,%1,%2,%3}, [%4];"
                 : "=r"(r[0]), "=r"(r[1]), "=r"(r[2]), "=r"(r[3]) : "r"(addr));
}

__device__ __forceinline__ void mma16816(float* d, const uint32_t* a, const uint32_t* b) {
    asm volatile("mma.sync.aligned.m16n8k16.row.col.f32.f16.f16.f32 "
                 "{%0,%1,%2,%3}, {%4,%5,%6,%7}, {%8,%9}, {%0,%1,%2,%3};"
                 : "+f"(d[0]), "+f"(d[1]), "+f"(d[2]), "+f"(d[3])
                 : "r"(a[0]), "r"(a[1]), "r"(a[2]), "r"(a[3]), "r"(b[0]), "r"(b[1]));
}

// ---------------------------------------------------------------------------
// Prep A: DFT-32 of weights -> embedded fp16 A: Ae = [[Re,-Im],[Im,Re]]
// ---------------------------------------------------------------------------
__global__ __launch_bounds__(256) void prepA(const float* __restrict__ w) {
    __shared__ float2 tw[32];
    int t = threadIdx.x;
    if (t < 32) { float s, c; sincospif(t * (1.0f / 16.0f), &s, &c); tw[t] = make_float2(c, s); }
    __syncthreads();

    int idx = blockIdx.x * 256 + t;            // p*1024 + q
    int p = idx >> 10, q = idx & 1023;

    float v[N_T];
    #pragma unroll
    for (int n = 0; n < N_T; n++) v[n] = w[n * PQ + idx];

    #pragma unroll 1
    for (int k = 0; k < NF; k++) {
        float re = 0.0f, im = 0.0f;
        int j = 0;
        #pragma unroll
        for (int n = 0; n < N_T; n++) {
            float2 wv = tw[j];
            re += v[n] * wv.x;
            im -= v[n] * wv.y;
            j = (j + k) & 31;
        }
        __half reh = __float2half(re);
        __half imh = __float2half(im);

        size_t base = (size_t)k * KE * KE;
        size_t r0 = base + (size_t)p * KE;
        size_t r1 = base + (size_t)(1024 + p) * KE;
        g_A[r0 + q]        = reh;
        g_A[r0 + 1024 + q] = __float2half(-im);
        g_A[r1 + q]        = imh;
        g_A[r1 + 1024 + q] = reh;
    }
}

// ---------------------------------------------------------------------------
// Prep B: DFT-32 of x -> fp16 B^T, K-major [m][kappa]; kappa<1024 Re, else Im.
// ---------------------------------------------------------------------------
__global__ __launch_bounds__(1024) void prepB(const float* __restrict__ x) {
    __shared__ float2 tw[32];
    __shared__ __half sre[32][33], sim[32][33];
    int t = threadIdx.x;
    if (t < 32) { float s, c; sincospif(t * (1.0f / 16.0f), &s, &c); tw[t] = make_float2(c, s); }
    __syncthreads();

    int bm = blockIdx.x & 31, bq = blockIdx.x >> 5;
    int lm = t & 31, lq = t >> 5;
    int q = bq * 32 + lq, m = bm * 32 + lm;

    float v[N_T];
    #pragma unroll
    for (int n = 0; n < N_T; n++) v[n] = x[(size_t)n * PQ + q * 1024 + m];

    #pragma unroll 1
    for (int k = 0; k < NF; k++) {
        float re = 0.0f, im = 0.0f;
        int j = 0;
        #pragma unroll
        for (int n = 0; n < N_T; n++) {
            float2 wv = tw[j];
            re += v[n] * wv.x;
            im -= v[n] * wv.y;
            j = (j + k) & 31;
        }

        __syncthreads();               // protect planes from previous k
        sre[lq][lm] = __float2half(re);
        sim[lq][lm] = __float2half(im);
        __syncthreads();

        // write transposed: row m' = bm*32+lq, col q' = bq*32+lm (coalesced over lm)
        size_t rowbase = (size_t)k * SIZE * KE + (size_t)(bm * 32 + lq) * KE + bq * 32;
        g_B[rowbase + lm]        = sre[lm][lq];
        g_B[rowbase + 1024 + lm] = sim[lm][lq];
    }
}

// ---------------------------------------------------------------------------
// mma.sync fp16 GEMM: D[2048x1024] = A*B per freq (fp32 acc)
// 128x128 CTA tile, 8 warps (4m x 2n), warp tile 32x64, 4-stage cp.async.
// ---------------------------------------------------------------------------
__global__ __launch_bounds__(256, 1) void tgemm() {
    extern __shared__ char dynsmem[];
    uint32_t sbase = (smem_u32(dynsmem) + 1023u) & ~1023u;

    const int t = threadIdx.x;
    const int lane = t & 31;
    const int wid = t >> 5;
    const int wm = wid >> 1, wn = wid & 1;
    const int m_warp = wm * 32, n_warp = wn * 64;

    const int kf = blockIdx.z;
    const size_t aoff = (size_t)kf * KE * KE + (size_t)blockIdx.y * BM * KE;
    const size_t boff = (size_t)kf * SIZE * KE + (size_t)blockIdx.x * BN * KE;

    // ldmatrix lane mappings
    const int rowA_off = (lane & 7) + ((lane >> 3) & 1) * 8;  // matrices 0/1 = m halves
    const int kselA    = lane >> 4;                            // matrices 2/3 = k halves
    const int rowB_off = (lane & 7) + ((lane >> 4) & 1) * 8;  // matrices 2/3 = n halves
    const int kselB    = (lane >> 3) & 1;                      // matrices 1/3 = k halves

    // per-chunk cooperative copy: 1024 units = 128 rows x 8 16B-chunks, 256 thr
    auto copy_chunk = [&](int c) {
        uint32_t sb = sbase + (uint32_t)(c & (NSTAGE - 1)) * STAGE_BYTES;
        size_t kcol = (size_t)c * KC;
        #pragma unroll
        for (int i = 0; i < 4; i++) {
            int u = t + i * 256;
            int r = u >> 3, c16 = u & 7;
            uint32_t sw = (uint32_t)(r * 128 + ((c16 ^ (r & 7)) << 4));
            size_t ga = aoff + (size_t)r * KE + kcol + c16 * 8;
            size_t gb = boff + (size_t)r * KE + kcol + c16 * 8;
            cpa16(sb + OFF_A + sw, g_A + ga);
            cpa16(sb + OFF_B + sw, g_B + gb);
        }
    };

    float acc[2][8][4];
    #pragma unroll
    for (int i = 0; i < 2; i++)
        #pragma unroll
        for (int j = 0; j < 8; j++)
            #pragma unroll
            for (int r = 0; r < 4; r++) acc[i][j][r] = 0.0f;

    copy_chunk(0); CP_COMMIT();
    copy_chunk(1); CP_COMMIT();
    copy_chunk(2); CP_COMMIT();

    for (int c = 0; c < NC; c++) {
        CP_WAIT2();
        __syncthreads();
        uint32_t sb = sbase + (uint32_t)(c & (NSTAGE - 1)) * STAGE_BYTES;

        #pragma unroll
        for (int ks = 0; ks < 4; ks++) {
            uint32_t ah[2][4], bh[4][4];
            #pragma unroll
            for (int mt = 0; mt < 2; mt++) {
                int row = m_warp + mt * 16 + rowA_off;
                int kch = ks * 2 + kselA;
                uint32_t off = (uint32_t)(row * 128 + (((kch) ^ (row & 7)) << 4));
                ldsm4(ah[mt], sb + OFF_A + off);
            }
            #pragma unroll
            for (int nt2 = 0; nt2 < 4; nt2++) {
                int row = n_warp + nt2 * 16 + rowB_off;
                int kch = ks * 2 + kselB;
                uint32_t off = (uint32_t)(row * 128 + (((kch) ^ (row & 7)) << 4));
                ldsm4(bh[nt2], sb + OFF_B + off);
            }
            #pragma unroll
            for (int mt = 0; mt < 2; mt++) {
                #pragma unroll
                for (int nt = 0; nt < 8; nt++) {
                    mma16816(acc[mt][nt], ah[mt], &bh[nt >> 1][(nt & 1) * 2]);
                }
            }
        }
        if (c + 3 < NC) copy_chunk(c + 3);
        CP_COMMIT();
    }

    // epilogue: planar C write (rows 0-1023 -> Cre, 1024-2047 -> Cim)
    const int qd = lane >> 2, rr = lane & 3;
    const int rowblk = blockIdx.y * BM;          // entire CTA tile is one plane
    float* plane = (rowblk < 1024) ? g_Cre : g_Cim;
    const size_t pbase = (size_t)kf * PQ + (size_t)((rowblk < 1024) ? rowblk : rowblk - 1024) * 1024
                         + blockIdx.x * BN;

    #pragma unroll
    for (int mt = 0; mt < 2; mt++) {
        #pragma unroll
        for (int half = 0; half < 2; half++) {
            int row = m_warp + mt * 16 + qd + half * 8;
            float* dst = plane + pbase + (size_t)row * 1024;
            #pragma unroll
            for (int nt = 0; nt < 8; nt++) {
                int n = n_warp + nt * 8 + rr * 2;
                *reinterpret_cast<float2*>(dst + n) =
                    make_float2(acc[mt][nt][half * 2], acc[mt][nt][half * 2 + 1]);
            }
        }
    }
}

// ---------------------------------------------------------------------------
// Inverse DFT-32 (hermitian) + bias
// ---------------------------------------------------------------------------
__global__ __launch_bounds__(256) void ifft32_bias_kernel(const float* __restrict__ bias,
                                                          float* __restrict__ out) {
    __shared__ float2 tw[32];
    int t = threadIdx.x;
    if (t < 32) { float s, c; sincospif(t * (1.0f / 16.0f), &s, &c); tw[t] = make_float2(c, s); }
    __syncthreads();

    int idx = blockIdx.x * 256 + t;

    float2 cv[NF];
    #pragma unroll
    for (int k = 0; k < NF; k++) {
        cv[k].x = g_Cre[(size_t)k * PQ + idx];
        cv[k].y = g_Cim[(size_t)k * PQ + idx];
    }
    #pragma unroll
    for (int k = 1; k < 16; k++) { cv[k].x *= 2.0f; cv[k].y *= 2.0f; }

    float b = bias[idx];

    #pragma unroll 1
    for (int n = 0; n < N_T; n++) {
        float s = cv[0].x + ((n & 1) ? -cv[16].x : cv[16].x);
        #pragma unroll
        for (int k = 1; k < 16; k++) {
            int jj = (k * n) & 31;
            float2 wv = tw[jj];
            s += cv[k].x * wv.x;
            s -= cv[k].y * wv.y;
        }
        out[n * PQ + idx] = s * (1.0f / 32.0f) + b;
    }
}

// ---------------------------------------------------------------------------
// Launch
// ---------------------------------------------------------------------------
extern "C" void kernel_launch(void* const* d_in, const int* in_sizes, int n_in,
                              void* d_out, int out_size) {
    const float* x    = (const float*)d_in[0];
    const float* w    = (const float*)d_in[1];
    const float* bias = (const float*)d_in[2];
    float*       out  = (float*)d_out;

    cudaFuncSetAttribute(tgemm, cudaFuncAttributeMaxDynamicSharedMemorySize, 132096);

    prepA<<<4096, 256>>>(w);
    prepB<<<1024, 1024>>>(x);

    dim3 gg(SIZE / BN, KE / BM, NF);   // (8, 16, 17)
    tgemm<<<gg, 256, 132096>>>();

    ifft32_bias_kernel<<<4096, 256>>>(bias, out);
}

// round 6
// speedup vs baseline: 5.1385x; 1.2355x over previous
#include <cuda_runtime.h>
#include <cuda_fp16.h>
#include <cstdint>

#define N_T 32
#define NF  17
#define SIZE 1024
#define PQ  1048576

// GEMM tiling: 128x128 CTA tile, 4 warps of 64x64, K=1024
#define BM 128
#define BN 128
#define KC 64               // fp16 K per chunk (128 bytes per row)
#define NC (SIZE / KC)      // 16 chunks
#define NSTAGE 3
#define STAGE_BYTES 32768   // A(16K)+B(16K)
#define OFF_A 0
#define OFF_B 16384

// ---------------------------------------------------------------------------
// Device scratch: 3 planes per freq (Ar, Ai, As) / (Br, Bi, Bs) / (P1,P2,P3)
// ---------------------------------------------------------------------------
__device__ __half g_A[(size_t)NF * 3 * PQ];   // [k][plane][p][q] row-major
__device__ __half g_B[(size_t)NF * 3 * PQ];   // [k][plane][m][q] (B^T K-major)
__device__ float  g_P[(size_t)NF * 3 * PQ];   // [k][prod][p][m]

// ---------------------------------------------------------------------------
// PTX helpers (baseline PTX only)
// ---------------------------------------------------------------------------
__device__ __forceinline__ uint32_t smem_u32(const void* p) {
    uint32_t a;
    asm("{ .reg .u64 t; cvta.to.shared.u64 t, %1; cvt.u32.u64 %0, t; }"
        : "=r"(a) : "l"(p));
    return a;
}

__device__ __forceinline__ void cpa16(uint32_t dst, const void* src) {
    asm volatile("cp.async.cg.shared.global [%0], [%1], 16;" :: "r"(dst), "l"(src) : "memory");
}
#define CP_COMMIT() asm volatile("cp.async.commit_group;" ::: "memory")
#define CP_WAIT1()  asm volatile("cp.async.wait_group 1;"  ::: "memory")

__device__ __forceinline__ void ldsm4(uint32_t* r, uint32_t addr) {
    asm volatile("ldmatrix.sync.aligned.m8n8.x4.shared.b16 {%0,%1,%2,%3}, [%4];"
                 : "=r"(r[0]), "=r"(r[1]), "=r"(r[2]), "=r"(r[3]) : "r"(addr));
}

__device__ __forceinline__ void mma16816(float* d, const uint32_t* a, const uint32_t* b) {
    asm volatile("mma.sync.aligned.m16n8k16.row.col.f32.f16.f16.f32 "
                 "{%0,%1,%2,%3}, {%4,%5,%6,%7}, {%8,%9}, {%0,%1,%2,%3};"
                 : "+f"(d[0]), "+f"(d[1]), "+f"(d[2]), "+f"(d[3])
                 : "r"(a[0]), "r"(a[1]), "r"(a[2]), "r"(a[3]), "r"(b[0]), "r"(b[1]));
}

// ---------------------------------------------------------------------------
// Prep A: DFT-32 of weights -> fp16 planes Ar, Ai, As=Ar+Ai per freq
// ---------------------------------------------------------------------------
__global__ __launch_bounds__(256) void prepA(const float* __restrict__ w) {
    __shared__ float2 tw[32];
    int t = threadIdx.x;
    if (t < 32) { float s, c; sincospif(t * (1.0f / 16.0f), &s, &c); tw[t] = make_float2(c, s); }
    __syncthreads();

    int idx = blockIdx.x * 256 + t;            // p*1024 + q

    float v[N_T];
    #pragma unroll
    for (int n = 0; n < N_T; n++) v[n] = w[n * PQ + idx];

    #pragma unroll 1
    for (int k = 0; k < NF; k++) {
        float re = 0.0f, im = 0.0f;
        int j = 0;
        #pragma unroll
        for (int n = 0; n < N_T; n++) {
            float2 wv = tw[j];
            re += v[n] * wv.x;
            im -= v[n] * wv.y;
            j = (j + k) & 31;
        }
        size_t base = (size_t)(k * 3) * PQ + idx;
        g_A[base]          = __float2half(re);
        g_A[base + PQ]     = __float2half(im);
        g_A[base + 2 * PQ] = __float2half(re + im);
    }
}

// ---------------------------------------------------------------------------
// Prep B: DFT-32 of x -> fp16 B^T planes (K-major [m][q]): Br, Bi, Bs
// ---------------------------------------------------------------------------
__global__ __launch_bounds__(1024) void prepB(const float* __restrict__ x) {
    __shared__ float2 tw[32];
    __shared__ __half sre[32][33], sim[32][33];
    int t = threadIdx.x;
    if (t < 32) { float s, c; sincospif(t * (1.0f / 16.0f), &s, &c); tw[t] = make_float2(c, s); }
    __syncthreads();

    int bm = blockIdx.x & 31, bq = blockIdx.x >> 5;
    int lm = t & 31, lq = t >> 5;
    int q = bq * 32 + lq, m = bm * 32 + lm;

    float v[N_T];
    #pragma unroll
    for (int n = 0; n < N_T; n++) v[n] = x[(size_t)n * PQ + q * 1024 + m];

    #pragma unroll 1
    for (int k = 0; k < NF; k++) {
        float re = 0.0f, im = 0.0f;
        int j = 0;
        #pragma unroll
        for (int n = 0; n < N_T; n++) {
            float2 wv = tw[j];
            re += v[n] * wv.x;
            im -= v[n] * wv.y;
            j = (j + k) & 31;
        }

        __syncthreads();               // protect tiles from previous k
        sre[lq][lm] = __float2half(re);
        sim[lq][lm] = __float2half(im);
        __syncthreads();

        // transposed write: row m' = bm*32+lq, col q' = bq*32+lm
        size_t rowbase = (size_t)(k * 3) * PQ + (size_t)(bm * 32 + lq) * 1024 + bq * 32 + lm;
        __half r2 = sre[lm][lq], i2 = sim[lm][lq];
        g_B[rowbase]          = r2;
        g_B[rowbase + PQ]     = i2;
        g_B[rowbase + 2 * PQ] = __hadd(r2, i2);
    }
}

// ---------------------------------------------------------------------------
// fp16 GEMM per (freq, product): P[z] = A[z] * B[z]^T, 1024^3, fp32 acc.
// 128 threads, 4 warps (2m x 2n), warp tile 64x64, 3-stage cp.async.
// ---------------------------------------------------------------------------
__global__ __launch_bounds__(128, 2) void tgemm() {
    extern __shared__ char dynsmem[];
    uint32_t sbase = (smem_u32(dynsmem) + 1023u) & ~1023u;

    const int t = threadIdx.x;
    const int lane = t & 31;
    const int wid = t >> 5;
    const int m_warp = (wid >> 1) * 64, n_warp = (wid & 1) * 64;

    const size_t zoff = (size_t)blockIdx.z * PQ;
    const size_t aoff = zoff + (size_t)blockIdx.y * BM * 1024;
    const size_t boff = zoff + (size_t)blockIdx.x * BN * 1024;

    // ldmatrix lane mappings
    const int rowA_off = (lane & 7) + ((lane >> 3) & 1) * 8;
    const int kselA    = lane >> 4;
    const int rowB_off = (lane & 7) + ((lane >> 4) & 1) * 8;
    const int kselB    = (lane >> 3) & 1;

    // per-chunk copy: A 128 rows + B 128 rows, 8 x 16B chunks each; 128 thr
    auto copy_chunk = [&](int c) {
        uint32_t sb = sbase + (uint32_t)(c % NSTAGE) * STAGE_BYTES;
        size_t kcol = (size_t)c * KC;
        #pragma unroll
        for (int i = 0; i < 8; i++) {
            int u = t + i * 128;
            int r = u >> 3, c16 = u & 7;
            uint32_t sw = (uint32_t)(r * 128 + ((c16 ^ (r & 7)) << 4));
            cpa16(sb + OFF_A + sw, g_A + aoff + (size_t)r * 1024 + kcol + c16 * 8);
            cpa16(sb + OFF_B + sw, g_B + boff + (size_t)r * 1024 + kcol + c16 * 8);
        }
    };

    float acc[4][8][4];
    #pragma unroll
    for (int i = 0; i < 4; i++)
        #pragma unroll
        for (int j = 0; j < 8; j++)
            #pragma unroll
            for (int r = 0; r < 4; r++) acc[i][j][r] = 0.0f;

    copy_chunk(0); CP_COMMIT();
    copy_chunk(1); CP_COMMIT();

    for (int c = 0; c < NC; c++) {
        CP_WAIT1();
        __syncthreads();
        uint32_t sb = sbase + (uint32_t)(c % NSTAGE) * STAGE_BYTES;

        #pragma unroll
        for (int ks = 0; ks < 4; ks++) {
            uint32_t ah[4][4], bh[4][4];
            #pragma unroll
            for (int mt = 0; mt < 4; mt++) {
                int row = m_warp + mt * 16 + rowA_off;
                int kch = ks * 2 + kselA;
                ldsm4(ah[mt], sb + OFF_A + (uint32_t)(row * 128 + ((kch ^ (row & 7)) << 4)));
            }
            #pragma unroll
            for (int nt2 = 0; nt2 < 4; nt2++) {
                int row = n_warp + nt2 * 16 + rowB_off;
                int kch = ks * 2 + kselB;
                ldsm4(bh[nt2], sb + OFF_B + (uint32_t)(row * 128 + ((kch ^ (row & 7)) << 4)));
            }
            #pragma unroll
            for (int mt = 0; mt < 4; mt++) {
                #pragma unroll
                for (int nt = 0; nt < 8; nt++) {
                    mma16816(acc[mt][nt], ah[mt], &bh[nt >> 1][(nt & 1) * 2]);
                }
            }
        }
        __syncthreads();
        if (c + 2 < NC) copy_chunk(c + 2);
        CP_COMMIT();
    }

    // epilogue
    const int qd = lane >> 2, rr = lane & 3;
    float* dstbase = g_P + zoff + (size_t)blockIdx.y * BM * 1024 + blockIdx.x * BN;
    #pragma unroll
    for (int mt = 0; mt < 4; mt++) {
        #pragma unroll
        for (int half = 0; half < 2; half++) {
            int row = m_warp + mt * 16 + qd + half * 8;
            float* dst = dstbase + (size_t)row * 1024;
            #pragma unroll
            for (int nt = 0; nt < 8; nt++) {
                int n = n_warp + nt * 8 + rr * 2;
                *reinterpret_cast<float2*>(dst + n) =
                    make_float2(acc[mt][nt][half * 2], acc[mt][nt][half * 2 + 1]);
            }
        }
    }
}

// ---------------------------------------------------------------------------
// Karatsuba combine + inverse DFT-32 (hermitian) + bias
// Cre = P1 - P2 ; Cim = P3 - P1 - P2
// ---------------------------------------------------------------------------
__global__ __launch_bounds__(256) void ifft32_bias_kernel(const float* __restrict__ bias,
                                                          float* __restrict__ out) {
    __shared__ float2 tw[32];
    int t = threadIdx.x;
    if (t < 32) { float s, c; sincospif(t * (1.0f / 16.0f), &s, &c); tw[t] = make_float2(c, s); }
    __syncthreads();

    int idx = blockIdx.x * 256 + t;

    float2 cv[NF];
    #pragma unroll
    for (int k = 0; k < NF; k++) {
        size_t base = (size_t)(k * 3) * PQ + idx;
        float p1 = g_P[base];
        float p2 = g_P[base + PQ];
        float p3 = g_P[base + 2 * PQ];
        cv[k].x = p1 - p2;
        cv[k].y = p3 - p1 - p2;
    }
    #pragma unroll
    for (int k = 1; k < 16; k++) { cv[k].x *= 2.0f; cv[k].y *= 2.0f; }

    float b = bias[idx];

    #pragma unroll 1
    for (int n = 0; n < N_T; n++) {
        float s = cv[0].x + ((n & 1) ? -cv[16].x : cv[16].x);
        #pragma unroll
        for (int k = 1; k < 16; k++) {
            int jj = (k * n) & 31;
            float2 wv = tw[jj];
            s += cv[k].x * wv.x;
            s -= cv[k].y * wv.y;
        }
        out[n * PQ + idx] = s * (1.0f / 32.0f) + b;
    }
}

// ---------------------------------------------------------------------------
// Launch
// ---------------------------------------------------------------------------
extern "C" void kernel_launch(void* const* d_in, const int* in_sizes, int n_in,
                              void* d_out, int out_size) {
    const float* x    = (const float*)d_in[0];
    const float* w    = (const float*)d_in[1];
    const float* bias = (const float*)d_in[2];
    float*       out  = (float*)d_out;

    cudaFuncSetAttribute(tgemm, cudaFuncAttributeMaxDynamicSharedMemorySize, 99328);

    prepA<<<4096, 256>>>(w);
    prepB<<<1024, 1024>>>(x);

    dim3 gg(SIZE / BN, SIZE / BM, NF * 3);   // (8, 8, 51)
    tgemm<<<gg, 128, 99328>>>();

    ifft32_bias_kernel<<<4096, 256>>>(bias, out);
}

// round 7
// speedup vs baseline: 5.8636x; 1.1411x over previous
#include <cuda_runtime.h>
#include <cuda_fp16.h>
#include <cstdint>

#define N_T 32
#define NF  17
#define SIZE 1024
#define PQ  1048576

// GEMM tiling: 128x128 CTA tile, 4 warps of 64x64, K=1024
#define BM 128
#define BN 128
#define KC 64
#define NC (SIZE / KC)      // 16 chunks
#define NSTAGE 3
#define STAGE_BYTES 32768   // A(16K)+B(16K)
#define OFF_A 0
#define OFF_B 16384
#define NPROD 47            // 15 freqs x 3 products + k=0,16 x 1 product

// ---------------------------------------------------------------------------
// Device scratch: 3 planes per freq (Ar, Ai, As) / (Br, Bi, Bs) / (P1,P2,P3)
// ---------------------------------------------------------------------------
__device__ __half g_A[(size_t)NF * 3 * PQ];   // [k][plane][p][q]
__device__ __half g_B[(size_t)NF * 3 * PQ];   // [k][plane][m][q] (B^T K-major)
__device__ float  g_P[(size_t)NF * 3 * PQ];   // [k][prod][p][m]

// ---------------------------------------------------------------------------
// PTX helpers (baseline PTX only)
// ---------------------------------------------------------------------------
__device__ __forceinline__ uint32_t smem_u32(const void* p) {
    uint32_t a;
    asm("{ .reg .u64 t; cvta.to.shared.u64 t, %1; cvt.u32.u64 %0, t; }"
        : "=r"(a) : "l"(p));
    return a;
}

__device__ __forceinline__ void cpa16(uint32_t dst, const void* src) {
    asm volatile("cp.async.cg.shared.global [%0], [%1], 16;" :: "r"(dst), "l"(src) : "memory");
}
#define CP_COMMIT() asm volatile("cp.async.commit_group;" ::: "memory")
#define CP_WAIT1()  asm volatile("cp.async.wait_group 1;"  ::: "memory")

__device__ __forceinline__ void ldsm4(uint32_t* r, uint32_t addr) {
    asm volatile("ldmatrix.sync.aligned.m8n8.x4.shared.b16 {%0,%1,%2,%3}, [%4];"
                 : "=r"(r[0]), "=r"(r[1]), "=r"(r[2]), "=r"(r[3]) : "r"(addr));
}

__device__ __forceinline__ void mma16816(float* d, const uint32_t* a, const uint32_t* b) {
    asm volatile("mma.sync.aligned.m16n8k16.row.col.f32.f16.f16.f32 "
                 "{%0,%1,%2,%3}, {%4,%5,%6,%7}, {%8,%9}, {%0,%1,%2,%3};"
                 : "+f"(d[0]), "+f"(d[1]), "+f"(d[2]), "+f"(d[3])
                 : "r"(a[0]), "r"(a[1]), "r"(a[2]), "r"(a[3]), "r"(b[0]), "r"(b[1]));
}

// ---------------------------------------------------------------------------
// Prep A: DFT-32 of weights -> fp16 planes Ar, Ai, As=Ar+Ai per freq
// (k=0,16 are real: only Ar written/used)
// ---------------------------------------------------------------------------
__global__ __launch_bounds__(256) void prepA(const float* __restrict__ w) {
    __shared__ float2 tw[32];
    int t = threadIdx.x;
    if (t < 32) { float s, c; sincospif(t * (1.0f / 16.0f), &s, &c); tw[t] = make_float2(c, s); }
    __syncthreads();

    int idx = blockIdx.x * 256 + t;

    float v[N_T];
    #pragma unroll
    for (int n = 0; n < N_T; n++) v[n] = w[n * PQ + idx];

    #pragma unroll 1
    for (int k = 0; k < NF; k++) {
        float re = 0.0f, im = 0.0f;
        int j = 0;
        #pragma unroll
        for (int n = 0; n < N_T; n++) {
            float2 wv = tw[j];
            re += v[n] * wv.x;
            im -= v[n] * wv.y;
            j = (j + k) & 31;
        }
        size_t base = (size_t)(k * 3) * PQ + idx;
        g_A[base] = __float2half(re);
        if (k != 0 && k != 16) {
            g_A[base + PQ]     = __float2half(im);
            g_A[base + 2 * PQ] = __float2half(re + im);
        }
    }
}

// ---------------------------------------------------------------------------
// Prep B: DFT-32 of x -> fp16 B^T planes (K-major [m][q]): Br, Bi, Bs
// ---------------------------------------------------------------------------
__global__ __launch_bounds__(1024) void prepB(const float* __restrict__ x) {
    __shared__ float2 tw[32];
    __shared__ __half sre[32][33], sim[32][33];
    int t = threadIdx.x;
    if (t < 32) { float s, c; sincospif(t * (1.0f / 16.0f), &s, &c); tw[t] = make_float2(c, s); }
    __syncthreads();

    int bm = blockIdx.x & 31, bq = blockIdx.x >> 5;
    int lm = t & 31, lq = t >> 5;
    int q = bq * 32 + lq, m = bm * 32 + lm;

    float v[N_T];
    #pragma unroll
    for (int n = 0; n < N_T; n++) v[n] = x[(size_t)n * PQ + q * 1024 + m];

    #pragma unroll 1
    for (int k = 0; k < NF; k++) {
        float re = 0.0f, im = 0.0f;
        int j = 0;
        #pragma unroll
        for (int n = 0; n < N_T; n++) {
            float2 wv = tw[j];
            re += v[n] * wv.x;
            im -= v[n] * wv.y;
            j = (j + k) & 31;
        }

        __syncthreads();
        sre[lq][lm] = __float2half(re);
        sim[lq][lm] = __float2half(im);
        __syncthreads();

        size_t rowbase = (size_t)(k * 3) * PQ + (size_t)(bm * 32 + lq) * 1024 + bq * 32 + lm;
        __half r2 = sre[lm][lq], i2 = sim[lm][lq];
        g_B[rowbase] = r2;
        if (k != 0 && k != 16) {
            g_B[rowbase + PQ]     = i2;
            g_B[rowbase + 2 * PQ] = __hadd(r2, i2);
        }
    }
}

// ---------------------------------------------------------------------------
// fp16 GEMM per product: P[z] = A[z] * B[z]^T, 1024^3, fp32 acc.
// z<45: freq 1+z/3, plane z%3 ; z=45: k=0 ; z=46: k=16 (real-only)
// ---------------------------------------------------------------------------
__global__ __launch_bounds__(128, 2) void tgemm() {
    extern __shared__ char dynsmem[];
    uint32_t sbase = (smem_u32(dynsmem) + 1023u) & ~1023u;

    const int t = threadIdx.x;
    const int lane = t & 31;
    const int wid = t >> 5;
    const int m_warp = (wid >> 1) * 64, n_warp = (wid & 1) * 64;

    int z = blockIdx.z, k, plane;
    if (z < 45) { int kq = z / 3; k = 1 + kq + (kq >> 4); plane = z - kq * 3; }  // skip k=16
    else { k = (z == 45) ? 0 : 16; plane = 0; }
    // note: kq ranges 0..14 -> k = 1..15 (kq>>4 is 0 for all); keep simple:
    // k = 1 + z/3 maps z/3 in 0..14 to k 1..15.

    const size_t zoff = (size_t)(k * 3 + plane) * PQ;
    const size_t aoff = zoff + (size_t)blockIdx.y * BM * 1024;
    const size_t boff = zoff + (size_t)blockIdx.x * BN * 1024;

    const int rowA_off = (lane & 7) + ((lane >> 3) & 1) * 8;
    const int kselA    = lane >> 4;
    const int rowB_off = (lane & 7) + ((lane >> 4) & 1) * 8;
    const int kselB    = (lane >> 3) & 1;

    auto copy_chunk = [&](int c) {
        uint32_t sb = sbase + (uint32_t)(c % NSTAGE) * STAGE_BYTES;
        size_t kcol = (size_t)c * KC;
        #pragma unroll
        for (int i = 0; i < 8; i++) {
            int u = t + i * 128;
            int r = u >> 3, c16 = u & 7;
            uint32_t sw = (uint32_t)(r * 128 + ((c16 ^ (r & 7)) << 4));
            cpa16(sb + OFF_A + sw, g_A + aoff + (size_t)r * 1024 + kcol + c16 * 8);
            cpa16(sb + OFF_B + sw, g_B + boff + (size_t)r * 1024 + kcol + c16 * 8);
        }
    };

    float acc[4][8][4];
    #pragma unroll
    for (int i = 0; i < 4; i++)
        #pragma unroll
        for (int j = 0; j < 8; j++)
            #pragma unroll
            for (int r = 0; r < 4; r++) acc[i][j][r] = 0.0f;

    copy_chunk(0); CP_COMMIT();
    copy_chunk(1); CP_COMMIT();

    for (int c = 0; c < NC; c++) {
        CP_WAIT1();
        __syncthreads();
        uint32_t sb = sbase + (uint32_t)(c % NSTAGE) * STAGE_BYTES;

        #pragma unroll
        for (int ks = 0; ks < 4; ks++) {
            uint32_t ah[4][4], bh[4][4];
            #pragma unroll
            for (int mt = 0; mt < 4; mt++) {
                int row = m_warp + mt * 16 + rowA_off;
                int kch = ks * 2 + kselA;
                ldsm4(ah[mt], sb + OFF_A + (uint32_t)(row * 128 + ((kch ^ (row & 7)) << 4)));
            }
            #pragma unroll
            for (int nt2 = 0; nt2 < 4; nt2++) {
                int row = n_warp + nt2 * 16 + rowB_off;
                int kch = ks * 2 + kselB;
                ldsm4(bh[nt2], sb + OFF_B + (uint32_t)(row * 128 + ((kch ^ (row & 7)) << 4)));
            }
            #pragma unroll
            for (int mt = 0; mt < 4; mt++) {
                #pragma unroll
                for (int nt = 0; nt < 8; nt++) {
                    mma16816(acc[mt][nt], ah[mt], &bh[nt >> 1][(nt & 1) * 2]);
                }
            }
        }
        // top-of-loop barrier already orders last iteration's ldsm reads
        // against the overwrite of stage (c+2)%3 — no second barrier needed.
        if (c + 2 < NC) copy_chunk(c + 2);
        CP_COMMIT();
    }

    const int qd = lane >> 2, rr = lane & 3;
    float* dstbase = g_P + zoff + (size_t)blockIdx.y * BM * 1024 + blockIdx.x * BN;
    #pragma unroll
    for (int mt = 0; mt < 4; mt++) {
        #pragma unroll
        for (int half = 0; half < 2; half++) {
            int row = m_warp + mt * 16 + qd + half * 8;
            float* dst = dstbase + (size_t)row * 1024;
            #pragma unroll
            for (int nt = 0; nt < 8; nt++) {
                int n = n_warp + nt * 8 + rr * 2;
                *reinterpret_cast<float2*>(dst + n) =
                    make_float2(acc[mt][nt][half * 2], acc[mt][nt][half * 2 + 1]);
            }
        }
    }
}

// ---------------------------------------------------------------------------
// Karatsuba combine + inverse DFT-32 (hermitian, even/odd split) + bias
// Cre = P1 - P2 ; Cim = P3 - P1 - P2 ; k=0,16: C = (P1, 0)
// out[n] = E(n)+O(n), out[n+16] = E(n)-O(n), n in [0,16)
// ---------------------------------------------------------------------------
__global__ __launch_bounds__(256) void ifft32_bias_kernel(const float* __restrict__ bias,
                                                          float* __restrict__ out) {
    __shared__ float2 tw[32];
    int t = threadIdx.x;
    if (t < 32) { float s, c; sincospif(t * (1.0f / 16.0f), &s, &c); tw[t] = make_float2(c, s); }
    __syncthreads();

    int idx = blockIdx.x * 256 + t;

    float2 cv[NF];
    cv[0]  = make_float2(g_P[(size_t)0 * PQ + idx], 0.0f);
    cv[16] = make_float2(g_P[(size_t)(16 * 3) * PQ + idx], 0.0f);
    #pragma unroll
    for (int k = 1; k < 16; k++) {
        size_t base = (size_t)(k * 3) * PQ + idx;
        float p1 = g_P[base];
        float p2 = g_P[base + PQ];
        float p3 = g_P[base + 2 * PQ];
        cv[k].x = 2.0f * (p1 - p2);
        cv[k].y = 2.0f * (p3 - p1 - p2);
    }

    float b = bias[idx];

    #pragma unroll 1
    for (int n = 0; n < 16; n++) {
        float E = cv[0].x + ((n & 1) ? -cv[16].x : cv[16].x);
        float O = 0.0f;
        #pragma unroll
        for (int k = 1; k < 16; k++) {
            int jj = (k * n) & 31;
            float2 wv = tw[jj];
            float term = cv[k].x * wv.x - cv[k].y * wv.y;
            if (k & 1) O += term; else E += term;
        }
        out[n * PQ + idx]        = (E + O) * (1.0f / 32.0f) + b;
        out[(n + 16) * PQ + idx] = (E - O) * (1.0f / 32.0f) + b;
    }
}

// ---------------------------------------------------------------------------
// Launch
// ---------------------------------------------------------------------------
extern "C" void kernel_launch(void* const* d_in, const int* in_sizes, int n_in,
                              void* d_out, int out_size) {
    const float* x    = (const float*)d_in[0];
    const float* w    = (const float*)d_in[1];
    const float* bias = (const float*)d_in[2];
    float*       out  = (float*)d_out;

    cudaFuncSetAttribute(tgemm, cudaFuncAttributeMaxDynamicSharedMemorySize, 99328);

    prepA<<<4096, 256>>>(w);
    prepB<<<1024, 1024>>>(x);

    dim3 gg(SIZE / BN, SIZE / BM, NPROD);   // (8, 8, 47)
    tgemm<<<gg, 128, 99328>>>();

    ifft32_bias_kernel<<<4096, 256>>>(bias, out);
}

// round 9
// speedup vs baseline: 6.7697x; 1.1545x over previous
#include <cuda_runtime.h>
#include <cuda_fp16.h>
#include <cstdint>

#define N_T 32
#define NF  17
#define SIZE 1024
#define PQ  1048576

// GEMM tiling: 128x128 CTA tile, 4 warps of 64x64, K=1024
#define BM 128
#define BN 128
#define KC 64
#define NC (SIZE / KC)      // 16 chunks
#define NSTAGE 3
#define STAGE_BYTES 32768   // A(16K)+B(16K)
#define OFF_A 0
#define OFF_B 16384
#define NPROD 47            // 15 freqs x 3 products + k=0,16 x 1 product

// Compile-time twiddles: TWC[j]=cos(2*pi*j/32), TWS[j]=sin(2*pi*j/32).
// __device__ constexpr: folds to FFMA immediates under full unroll.
__device__ constexpr float TWC[32] = {
     1.00000000f,  0.98078528f,  0.92387953f,  0.83146961f,
     0.70710678f,  0.55557023f,  0.38268343f,  0.19509032f,
     0.00000000f, -0.19509032f, -0.38268343f, -0.55557023f,
    -0.70710678f, -0.83146961f, -0.92387953f, -0.98078528f,
    -1.00000000f, -0.98078528f, -0.92387953f, -0.83146961f,
    -0.70710678f, -0.55557023f, -0.38268343f, -0.19509032f,
     0.00000000f,  0.19509032f,  0.38268343f,  0.55557023f,
     0.70710678f,  0.83146961f,  0.92387953f,  0.98078528f
};
__device__ constexpr float TWS[32] = {
     0.00000000f,  0.19509032f,  0.38268343f,  0.55557023f,
     0.70710678f,  0.83146961f,  0.92387953f,  0.98078528f,
     1.00000000f,  0.98078528f,  0.92387953f,  0.83146961f,
     0.70710678f,  0.55557023f,  0.38268343f,  0.19509032f,
     0.00000000f, -0.19509032f, -0.38268343f, -0.55557023f,
    -0.70710678f, -0.83146961f, -0.92387953f, -0.98078528f,
    -1.00000000f, -0.98078528f, -0.92387953f, -0.83146961f,
    -0.70710678f, -0.55557023f, -0.38268343f, -0.19509032f
};

// ---------------------------------------------------------------------------
// Device scratch: 3 planes per freq (Ar, Ai, As) / (Br, Bi, Bs) / (P1,P2,P3)
// ---------------------------------------------------------------------------
__device__ __half g_A[(size_t)NF * 3 * PQ];   // [k][plane][p][q]
__device__ __half g_B[(size_t)NF * 3 * PQ];   // [k][plane][m][q] (B^T K-major)
__device__ __half g_P[(size_t)NF * 3 * PQ];   // [k][prod][p][m]  (fp16 products)

// ---------------------------------------------------------------------------
// PTX helpers (baseline PTX only)
// ---------------------------------------------------------------------------
__device__ __forceinline__ uint32_t smem_u32(const void* p) {
    uint32_t a;
    asm("{ .reg .u64 t; cvta.to.shared.u64 t, %1; cvt.u32.u64 %0, t; }"
        : "=r"(a) : "l"(p));
    return a;
}

__device__ __forceinline__ void cpa16(uint32_t dst, const void* src) {
    asm volatile("cp.async.cg.shared.global [%0], [%1], 16;" :: "r"(dst), "l"(src) : "memory");
}
#define CP_COMMIT() asm volatile("cp.async.commit_group;" ::: "memory")
#define CP_WAIT1()  asm volatile("cp.async.wait_group 1;"  ::: "memory")

__device__ __forceinline__ void ldsm4(uint32_t* r, uint32_t addr) {
    asm volatile("ldmatrix.sync.aligned.m8n8.x4.shared.b16 {%0,%1,%2,%3}, [%4];"
                 : "=r"(r[0]), "=r"(r[1]), "=r"(r[2]), "=r"(r[3]) : "r"(addr));
}

__device__ __forceinline__ void mma16816(float* d, const uint32_t* a, const uint32_t* b) {
    asm volatile("mma.sync.aligned.m16n8k16.row.col.f32.f16.f16.f32 "
                 "{%0,%1,%2,%3}, {%4,%5,%6,%7}, {%8,%9}, {%0,%1,%2,%3};"
                 : "+f"(d[0]), "+f"(d[1]), "+f"(d[2]), "+f"(d[3])
                 : "r"(a[0]), "r"(a[1]), "r"(a[2]), "r"(a[3]), "r"(b[0]), "r"(b[1]));
}

// ---------------------------------------------------------------------------
// Prep A: DFT-32 of weights -> fp16 planes Ar, Ai, As=Ar+Ai per freq
// Even/odd fold: X[k] = sum_{n<16} (v[n] + (-1)^k v[n+16]) w^{kn}
// ---------------------------------------------------------------------------
__global__ __launch_bounds__(256) void prepA(const float* __restrict__ w) {
    int idx = blockIdx.x * 256 + threadIdx.x;

    float v[N_T];
    #pragma unroll
    for (int n = 0; n < N_T; n++) v[n] = w[n * PQ + idx];

    float e[16], o[16];
    #pragma unroll
    for (int n = 0; n < 16; n++) { e[n] = v[n] + v[n + 16]; o[n] = v[n] - v[n + 16]; }

    #pragma unroll
    for (int k = 0; k < NF; k++) {
        float re = 0.0f, im = 0.0f;
        #pragma unroll
        for (int n = 0; n < 16; n++) {
            float s = (k & 1) ? o[n] : e[n];
            re += s * TWC[(k * n) & 31];
            im -= s * TWS[(k * n) & 31];
        }
        size_t base = (size_t)(k * 3) * PQ + idx;
        g_A[base] = __float2half(re);
        if (k != 0 && k != 16) {
            g_A[base + PQ]     = __float2half(im);
            g_A[base + 2 * PQ] = __float2half(re + im);
        }
    }
}

// ---------------------------------------------------------------------------
// Prep B: DFT-32 of x -> fp16 B^T planes (K-major [m][q]): Br, Bi, Bs
// ---------------------------------------------------------------------------
__global__ __launch_bounds__(1024) void prepB(const float* __restrict__ x) {
    __shared__ __half sre[32][33], sim[32][33];
    int t = threadIdx.x;

    int bm = blockIdx.x & 31, bq = blockIdx.x >> 5;
    int lm = t & 31, lq = t >> 5;
    int q = bq * 32 + lq, m = bm * 32 + lm;

    float v[N_T];
    #pragma unroll
    for (int n = 0; n < N_T; n++) v[n] = x[(size_t)n * PQ + q * 1024 + m];

    float e[16], o[16];
    #pragma unroll
    for (int n = 0; n < 16; n++) { e[n] = v[n] + v[n + 16]; o[n] = v[n] - v[n + 16]; }

    #pragma unroll 1
    for (int k = 0; k < NF; k++) {
        float re = 0.0f, im = 0.0f;
        if (k & 1) {
            #pragma unroll
            for (int n = 0; n < 16; n++) {
                re += o[n] * TWC[(k * n) & 31];
                im -= o[n] * TWS[(k * n) & 31];
            }
        } else {
            #pragma unroll
            for (int n = 0; n < 16; n++) {
                re += e[n] * TWC[(k * n) & 31];
                im -= e[n] * TWS[(k * n) & 31];
            }
        }

        __syncthreads();
        sre[lq][lm] = __float2half(re);
        sim[lq][lm] = __float2half(im);
        __syncthreads();

        size_t rowbase = (size_t)(k * 3) * PQ + (size_t)(bm * 32 + lq) * 1024 + bq * 32 + lm;
        __half r2 = sre[lm][lq], i2 = sim[lm][lq];
        g_B[rowbase] = r2;
        if (k != 0 && k != 16) {
            g_B[rowbase + PQ]     = i2;
            g_B[rowbase + 2 * PQ] = __hadd(r2, i2);
        }
    }
}

// ---------------------------------------------------------------------------
// fp16 GEMM per product: P[z] = A[z] * B[z]^T, 1024^3, fp32 acc, fp16 out.
// z<45: freq 1+z/3, plane z%3 ; z=45: k=0 ; z=46: k=16 (real-only)
// ---------------------------------------------------------------------------
__global__ __launch_bounds__(128, 2) void tgemm() {
    extern __shared__ char dynsmem[];
    uint32_t sbase = (smem_u32(dynsmem) + 1023u) & ~1023u;

    const int t = threadIdx.x;
    const int lane = t & 31;
    const int wid = t >> 5;
    const int m_warp = (wid >> 1) * 64, n_warp = (wid & 1) * 64;

    int z = blockIdx.z, k, plane;
    if (z < 45) { k = 1 + z / 3; plane = z % 3; }
    else { k = (z == 45) ? 0 : 16; plane = 0; }

    const size_t zoff = (size_t)(k * 3 + plane) * PQ;
    const size_t aoff = zoff + (size_t)blockIdx.y * BM * 1024;
    const size_t boff = zoff + (size_t)blockIdx.x * BN * 1024;

    const int rowA_off = (lane & 7) + ((lane >> 3) & 1) * 8;
    const int kselA    = lane >> 4;
    const int rowB_off = (lane & 7) + ((lane >> 4) & 1) * 8;
    const int kselB    = (lane >> 3) & 1;

    auto copy_chunk = [&](int c) {
        uint32_t sb = sbase + (uint32_t)(c % NSTAGE) * STAGE_BYTES;
        size_t kcol = (size_t)c * KC;
        #pragma unroll
        for (int i = 0; i < 8; i++) {
            int u = t + i * 128;
            int r = u >> 3, c16 = u & 7;
            uint32_t sw = (uint32_t)(r * 128 + ((c16 ^ (r & 7)) << 4));
            cpa16(sb + OFF_A + sw, g_A + aoff + (size_t)r * 1024 + kcol + c16 * 8);
            cpa16(sb + OFF_B + sw, g_B + boff + (size_t)r * 1024 + kcol + c16 * 8);
        }
    };

    float acc[4][8][4];
    #pragma unroll
    for (int i = 0; i < 4; i++)
        #pragma unroll
        for (int j = 0; j < 8; j++)
            #pragma unroll
            for (int r = 0; r < 4; r++) acc[i][j][r] = 0.0f;

    copy_chunk(0); CP_COMMIT();
    copy_chunk(1); CP_COMMIT();

    for (int c = 0; c < NC; c++) {
        CP_WAIT1();
        __syncthreads();
        uint32_t sb = sbase + (uint32_t)(c % NSTAGE) * STAGE_BYTES;

        #pragma unroll
        for (int ks = 0; ks < 4; ks++) {
            uint32_t ah[4][4], bh[4][4];
            #pragma unroll
            for (int mt = 0; mt < 4; mt++) {
                int row = m_warp + mt * 16 + rowA_off;
                int kch = ks * 2 + kselA;
                ldsm4(ah[mt], sb + OFF_A + (uint32_t)(row * 128 + ((kch ^ (row & 7)) << 4)));
            }
            #pragma unroll
            for (int nt2 = 0; nt2 < 4; nt2++) {
                int row = n_warp + nt2 * 16 + rowB_off;
                int kch = ks * 2 + kselB;
                ldsm4(bh[nt2], sb + OFF_B + (uint32_t)(row * 128 + ((kch ^ (row & 7)) << 4)));
            }
            #pragma unroll
            for (int mt = 0; mt < 4; mt++) {
                #pragma unroll
                for (int nt = 0; nt < 8; nt++) {
                    mma16816(acc[mt][nt], ah[mt], &bh[nt >> 1][(nt & 1) * 2]);
                }
            }
        }
        if (c + 2 < NC) copy_chunk(c + 2);
        CP_COMMIT();
    }

    // epilogue: fp16 output (half2 stores of adjacent columns)
    const int qd = lane >> 2, rr = lane & 3;
    __half* dstbase = g_P + zoff + (size_t)blockIdx.y * BM * 1024 + blockIdx.x * BN;
    #pragma unroll
    for (int mt = 0; mt < 4; mt++) {
        #pragma unroll
        for (int half = 0; half < 2; half++) {
            int row = m_warp + mt * 16 + qd + half * 8;
            __half* dst = dstbase + (size_t)row * 1024;
            #pragma unroll
            for (int nt = 0; nt < 8; nt++) {
                int n = n_warp + nt * 8 + rr * 2;
                *reinterpret_cast<__half2*>(dst + n) =
                    __floats2half2_rn(acc[mt][nt][half * 2], acc[mt][nt][half * 2 + 1]);
            }
        }
    }
}

// ---------------------------------------------------------------------------
// Karatsuba combine + inverse DFT-32 (hermitian, even/odd split) + bias
// Cre = P1 - P2 ; Cim = P3 - P1 - P2 ; k=0,16: C = (P1, 0)
// out[n] = E(n)+O(n), out[n+16] = E(n)-O(n), n in [0,16)
// ---------------------------------------------------------------------------
__global__ __launch_bounds__(256) void ifft32_bias_kernel(const float* __restrict__ bias,
                                                          float* __restrict__ out) {
    int idx = blockIdx.x * 256 + threadIdx.x;

    float cvx[NF], cvy[NF];
    cvx[0]  = __half2float(g_P[(size_t)0 * PQ + idx]);          cvy[0]  = 0.0f;
    cvx[16] = __half2float(g_P[(size_t)(16 * 3) * PQ + idx]);   cvy[16] = 0.0f;
    #pragma unroll
    for (int k = 1; k < 16; k++) {
        size_t base = (size_t)(k * 3) * PQ + idx;
        float p1 = __half2float(g_P[base]);
        float p2 = __half2float(g_P[base + PQ]);
        float p3 = __half2float(g_P[base + 2 * PQ]);
        cvx[k] = 2.0f * (p1 - p2);
        cvy[k] = 2.0f * (p3 - p1 - p2);
    }

    float b = bias[idx];

    #pragma unroll
    for (int n = 0; n < 16; n++) {
        float E = cvx[0] + ((n & 1) ? -cvx[16] : cvx[16]);
        float O = 0.0f;
        #pragma unroll
        for (int k = 1; k < 16; k++) {
            float term = cvx[k] * TWC[(k * n) & 31] - cvy[k] * TWS[(k * n) & 31];
            if (k & 1) O += term; else E += term;
        }
        out[n * PQ + idx]        = (E + O) * (1.0f / 32.0f) + b;
        out[(n + 16) * PQ + idx] = (E - O) * (1.0f / 32.0f) + b;
    }
}

// ---------------------------------------------------------------------------
// Launch
// ---------------------------------------------------------------------------
extern "C" void kernel_launch(void* const* d_in, const int* in_sizes, int n_in,
                              void* d_out, int out_size) {
    const float* x    = (const float*)d_in[0];
    const float* w    = (const float*)d_in[1];
    const float* bias = (const float*)d_in[2];
    float*       out  = (float*)d_out;

    cudaFuncSetAttribute(tgemm, cudaFuncAttributeMaxDynamicSharedMemorySize, 99328);

    prepA<<<4096, 256>>>(w);
    prepB<<<1024, 1024>>>(x);

    dim3 gg(SIZE / BN, SIZE / BM, NPROD);   // (8, 8, 47)
    tgemm<<<gg, 128, 99328>>>();

    ifft32_bias_kernel<<<4096, 256>>>(bias, out);
}